// round 16
// baseline (speedup 1.0000x reference)
#include <cuda_runtime.h>
#include <cuda_bf16.h>
#include <cuda_fp16.h>

#define Bq 2
#define Nq 2048
#define Hq 16
#define DHq 64
#define Dq 1024
#define HDq (Hq * DHq)   // 1024
#define Mq (Bq * Nq)     // 4096

#define PLX ((size_t)Mq * Dq)
#define PLW ((size_t)Dq * Dq)
#define PLA ((size_t)Mq * HDq)

// bf16 split planes
__device__ __nv_bfloat16 g_xb0[PLX], g_xb1[PLX];
__device__ __nv_bfloat16 g_wtb[8 * PLW];          // 4 weights x 2 planes, transposed [n][k]
__device__ __nv_bfloat16 g_qb0[PLA], g_qb1[PLA];
__device__ __nv_bfloat16 g_kb0[PLA], g_kb1[PLA];
__device__ __half        g_vh0[PLA];              // V single fp16 plane
__device__ __nv_bfloat16 g_ab0[PLA], g_ab1[PLA];

// ---------------------------------------------------------------------------
// helpers
// ---------------------------------------------------------------------------
__device__ __forceinline__ float bf_round(float x)
{
    return __bfloat162float(__float2bfloat16(x));
}

__device__ __forceinline__ float ex2(float x)
{
    float r;
    asm("ex2.approx.f32 %0, %1;" : "=f"(r) : "f"(x));
    return r;
}

#define PK_BF2(d, a, b) \
    asm("cvt.rn.bf16x2.f32 %0, %1, %2;" : "=r"(d) : "f"(b), "f"(a))
#define PK_HF2(d, a, b) \
    asm("cvt.rn.f16x2.f32 %0, %1, %2;" : "=r"(d) : "f"(b), "f"(a))

#define MMA_BF16(d, a, b0_, b1_)                                              \
    asm volatile("mma.sync.aligned.m16n8k16.row.col.f32.bf16.bf16.f32 "       \
                 "{%0,%1,%2,%3}, {%4,%5,%6,%7}, {%8,%9}, {%0,%1,%2,%3};"      \
                 : "+f"(d[0]), "+f"(d[1]), "+f"(d[2]), "+f"(d[3])             \
                 : "r"(a[0]), "r"(a[1]), "r"(a[2]), "r"(a[3]),                \
                   "r"(b0_), "r"(b1_))

#define MMA_F16(d, a, b0_, b1_)                                               \
    asm volatile("mma.sync.aligned.m16n8k16.row.col.f32.f16.f16.f32 "         \
                 "{%0,%1,%2,%3}, {%4,%5,%6,%7}, {%8,%9}, {%0,%1,%2,%3};"      \
                 : "+f"(d[0]), "+f"(d[1]), "+f"(d[2]), "+f"(d[3])             \
                 : "r"(a[0]), "r"(a[1]), "r"(a[2]), "r"(a[3]),                \
                   "r"(b0_), "r"(b1_))

#define LDSM_X4(r0, r1, r2, r3, addr)                                         \
    asm volatile("ldmatrix.sync.aligned.m8n8.x4.shared.b16 {%0,%1,%2,%3}, [%4];" \
                 : "=r"(r0), "=r"(r1), "=r"(r2), "=r"(r3) : "r"(addr))

#define LDSM_T_X4(r0, r1, r2, r3, addr)                                       \
    asm volatile("ldmatrix.sync.aligned.m8n8.x4.trans.shared.b16 {%0,%1,%2,%3}, [%4];" \
                 : "=r"(r0), "=r"(r1), "=r"(r2), "=r"(r3) : "r"(addr))

#define CP_A16(dst, src) \
    asm volatile("cp.async.cg.shared.global [%0], [%1], 16;" :: "r"(dst), "l"(src))
#define CP_COMMIT() asm volatile("cp.async.commit_group;")
#define CP_WAIT0()  asm volatile("cp.async.wait_group 0;" ::: "memory")
#define CP_WAIT1()  asm volatile("cp.async.wait_group 1;" ::: "memory")

// ---------------------------------------------------------------------------
// split kernels
// ---------------------------------------------------------------------------
__global__ __launch_bounds__(256) void split_x_b(const float* __restrict__ in)
{
    size_t i = (size_t)blockIdx.x * 256 + threadIdx.x;   // over float4
    float4 v = ((const float4*)in)[i];
    float h0 = bf_round(v.x), h1 = bf_round(v.y), h2 = bf_round(v.z), h3 = bf_round(v.w);
    unsigned u;
    PK_BF2(u, h0, h1);                 *(unsigned*)(g_xb0 + i * 4)     = u;
    PK_BF2(u, h2, h3);                 *(unsigned*)(g_xb0 + i * 4 + 2) = u;
    PK_BF2(u, v.x - h0, v.y - h1);     *(unsigned*)(g_xb1 + i * 4)     = u;
    PK_BF2(u, v.z - h2, v.w - h3);     *(unsigned*)(g_xb1 + i * 4 + 2) = u;
}

// all 4 weights in one launch: transpose + split via smem tile
__global__ __launch_bounds__(256) void split_wT_all(const float* __restrict__ Wq,
                                                    const float* __restrict__ Wk,
                                                    const float* __restrict__ Wv,
                                                    const float* __restrict__ Wo)
{
    __shared__ float ts[64][68];
    const int w = blockIdx.z;
    const float* W = (w == 0) ? Wq : (w == 1) ? Wk : (w == 2) ? Wv : Wo;
    const int tid = threadIdx.x;
    const int n0 = blockIdx.x * 64, k0 = blockIdx.y * 64;

#pragma unroll
    for (int i = 0; i < 4; i++) {
        int idx = i * 256 + tid;
        int kr = idx >> 4, c4 = idx & 15;
        float4 v = *(const float4*)(W + (size_t)(k0 + kr) * Dq + n0 + c4 * 4);
        ts[c4 * 4 + 0][kr] = v.x;
        ts[c4 * 4 + 1][kr] = v.y;
        ts[c4 * 4 + 2][kr] = v.z;
        ts[c4 * 4 + 3][kr] = v.w;
    }
    __syncthreads();

    const int n = tid >> 2, kc = (tid & 3) * 16;
    unsigned u0[8], u1[8];
#pragma unroll
    for (int j = 0; j < 8; j++) {
        float v0 = ts[n][kc + 2 * j], v1 = ts[n][kc + 2 * j + 1];
        float h0 = bf_round(v0), h1 = bf_round(v1);
        PK_BF2(u0[j], h0, h1);
        PK_BF2(u1[j], v0 - h0, v1 - h1);
    }
    __nv_bfloat16* d0 = g_wtb + (size_t)(w * 2 + 0) * PLW + (size_t)(n0 + n) * Dq + k0 + kc;
    __nv_bfloat16* d1 = g_wtb + (size_t)(w * 2 + 1) * PLW + (size_t)(n0 + n) * Dq + k0 + kc;
    *(uint4*)(d0)     = make_uint4(u0[0], u0[1], u0[2], u0[3]);
    *(uint4*)(d0 + 8) = make_uint4(u0[4], u0[5], u0[6], u0[7]);
    *(uint4*)(d1)     = make_uint4(u1[0], u1[1], u1[2], u1[3]);
    *(uint4*)(d1 + 8) = make_uint4(u1[4], u1[5], u1[6], u1[7]);
}

// ---------------------------------------------------------------------------
// bf16x3 m16n8k16 GEMM, BK=32, 2-stage cp.async (R10, proven).
// Epilogues: bf16 planes (Cb0) / fp16 single plane (Ch0) / fp32 + bias (Cf).
// ---------------------------------------------------------------------------
#define TPL 10240
#define STAGE_B 40960
#define GEMMP_SMEM (2 * STAGE_B)   // 81920

__device__ __forceinline__ void gemm_pipe_bf(const __nv_bfloat16* __restrict__ Ab0,
                                             const __nv_bfloat16* __restrict__ Ab1,
                                             const __nv_bfloat16* __restrict__ Wb0,
                                             const __nv_bfloat16* __restrict__ Wb1,
                                             __nv_bfloat16* __restrict__ Cb0,
                                             __nv_bfloat16* __restrict__ Cb1,
                                             __half* __restrict__ Ch0,
                                             float* __restrict__ Cf,
                                             const float* __restrict__ bias,
                                             int rowBlk, int colBlk)
{
    extern __shared__ float sm[];
    const unsigned smb = (unsigned)__cvta_generic_to_shared(sm);
    const int tid = threadIdx.x;
    const int wid = tid >> 5, lane = tid & 31;
    const int g = lane >> 2, t = lane & 3;
    const int wm = (wid & 3) * 32, wn = (wid >> 2) * 64;

    const size_t arow = (size_t)rowBlk * 128;
    const int ccol = colBlk * 128;

    const int quad = lane >> 3, lrow = lane & 7;
    const unsigned lmoff = (unsigned)(((quad & 1) * 8 + lrow) * 80 + (quad >> 1) * 16);

    float acc[2][8][4] = {};

#define PREFB(st, k0)                                                          \
    {                                                                          \
        unsigned base = smb + (st) * STAGE_B;                                  \
        _Pragma("unroll")                                                      \
        for (int i_ = 0; i_ < 2; i_++) {                                       \
            int idx = tid * 2 + i_;                                            \
            int r = idx >> 2, c4 = idx & 3;                                    \
            unsigned so = (unsigned)(r * 80 + c4 * 16);                        \
            CP_A16(base + 0 * TPL + so, Ab0 + (arow + r) * Dq + (k0) + c4 * 8);\
            CP_A16(base + 1 * TPL + so, Ab1 + (arow + r) * Dq + (k0) + c4 * 8);\
            CP_A16(base + 2 * TPL + so, Wb0 + (size_t)(ccol + r) * Dq + (k0) + c4 * 8); \
            CP_A16(base + 3 * TPL + so, Wb1 + (size_t)(ccol + r) * Dq + (k0) + c4 * 8); \
        }                                                                      \
    }

    PREFB(0, 0);
    CP_COMMIT();

    const int nch = Dq / 32;   // 32
    for (int chn = 0; chn < nch; chn++) {
        if (chn + 1 < nch) {
            PREFB((chn + 1) & 1, (chn + 1) * 32);
            CP_COMMIT();
            CP_WAIT1();
        } else {
            CP_WAIT0();
        }
        __syncthreads();

        const unsigned stg = smb + (chn & 1) * STAGE_B;

#pragma unroll
        for (int half = 0; half < 2; half++) {
            const unsigned co = (unsigned)(half * 32);
            unsigned af0[2][4], af1[2][4];
#pragma unroll
            for (int mt = 0; mt < 2; mt++) {
                unsigned ao = stg + (unsigned)((wm + mt * 16) * 80) + lmoff + co;
                LDSM_X4(af0[mt][0], af0[mt][1], af0[mt][2], af0[mt][3], ao);
                LDSM_X4(af1[mt][0], af1[mt][1], af1[mt][2], af1[mt][3], ao + TPL);
            }
            unsigned bf0[4][4], bf1[4][4];
#pragma unroll
            for (int np = 0; np < 4; np++) {
                unsigned wo = stg + 2 * TPL + (unsigned)((wn + np * 16) * 80) + lmoff + co;
                LDSM_X4(bf0[np][0], bf0[np][1], bf0[np][2], bf0[np][3], wo);
                LDSM_X4(bf1[np][0], bf1[np][1], bf1[np][2], bf1[np][3], wo + TPL);
            }
#pragma unroll
            for (int mt = 0; mt < 2; mt++)
#pragma unroll
                for (int nt = 0; nt < 8; nt++)
                    MMA_BF16(acc[mt][nt], af0[mt], bf0[nt >> 1][nt & 1], bf0[nt >> 1][(nt & 1) + 2]);
#pragma unroll
            for (int mt = 0; mt < 2; mt++)
#pragma unroll
                for (int nt = 0; nt < 8; nt++)
                    MMA_BF16(acc[mt][nt], af1[mt], bf0[nt >> 1][nt & 1], bf0[nt >> 1][(nt & 1) + 2]);
#pragma unroll
            for (int mt = 0; mt < 2; mt++)
#pragma unroll
                for (int nt = 0; nt < 8; nt++)
                    MMA_BF16(acc[mt][nt], af0[mt], bf1[nt >> 1][nt & 1], bf1[nt >> 1][(nt & 1) + 2]);
        }
        __syncthreads();
    }

#pragma unroll
    for (int mt = 0; mt < 2; mt++) {
        size_t r0 = arow + wm + mt * 16 + g;
#pragma unroll
        for (int nt = 0; nt < 8; nt++) {
            int c = ccol + wn + nt * 8 + 2 * t;
            float v0 = acc[mt][nt][0], v1 = acc[mt][nt][1];
            float v2 = acc[mt][nt][2], v3 = acc[mt][nt][3];
            if (Ch0) {
                unsigned u;
                PK_HF2(u, v0, v1); *(unsigned*)(Ch0 + r0 * Dq + c)       = u;
                PK_HF2(u, v2, v3); *(unsigned*)(Ch0 + (r0 + 8) * Dq + c) = u;
            } else if (Cb0) {
                float h0 = bf_round(v0), h1 = bf_round(v1);
                float h2 = bf_round(v2), h3 = bf_round(v3);
                unsigned u;
                PK_BF2(u, h0, h1);           *(unsigned*)(Cb0 + r0 * Dq + c) = u;
                PK_BF2(u, v0 - h0, v1 - h1); *(unsigned*)(Cb1 + r0 * Dq + c) = u;
                PK_BF2(u, h2, h3);           *(unsigned*)(Cb0 + (r0 + 8) * Dq + c) = u;
                PK_BF2(u, v2 - h2, v3 - h3); *(unsigned*)(Cb1 + (r0 + 8) * Dq + c) = u;
            } else {
                float b0 = bias[c], b1 = bias[c + 1];
                *(float2*)(Cf + r0 * Dq + c)       = make_float2(v0 + b0, v1 + b1);
                *(float2*)(Cf + (r0 + 8) * Dq + c) = make_float2(v2 + b0, v3 + b1);
            }
        }
    }
#undef PREFB
}

__global__ __launch_bounds__(256, 2) void qkv_gemm_p()
{
    int w = blockIdx.x >> 3, colBlk = blockIdx.x & 7;
    __nv_bfloat16* C0 = (w == 0) ? g_qb0 : (w == 1) ? g_kb0 : nullptr;
    __nv_bfloat16* C1 = (w == 0) ? g_qb1 : (w == 1) ? g_kb1 : nullptr;
    __half* H0 = (w == 2) ? g_vh0 : nullptr;
    gemm_pipe_bf(g_xb0, g_xb1,
                 g_wtb + (size_t)(w * 2) * PLW, g_wtb + (size_t)(w * 2 + 1) * PLW,
                 C0, C1, H0, nullptr, nullptr, blockIdx.y, colBlk);
}

__global__ __launch_bounds__(256, 2) void out_proj_p(const float* __restrict__ bo,
                                                     float* __restrict__ out)
{
    gemm_pipe_bf(g_ab0, g_ab1,
                 g_wtb + (size_t)6 * PLW, g_wtb + (size_t)7 * PLW,
                 nullptr, nullptr, nullptr, out, bo, blockIdx.y, blockIdx.x);
}

// ---------------------------------------------------------------------------
// flash attention: S bf16x3, P fp16, V single fp16 plane (PV = 1 pass).
// BR=64 / 4 warps / 3 CTAs per SM; Q frags persistent; 2-stage K/V ring.
// smem per stage: K0 K1 V0 = 3 planes x 9216 B = 27648; 2 stages = 55296.
// ---------------------------------------------------------------------------
#define VRB 144
#define FL_PL 9216
#define FL_STG_SZ (3 * FL_PL) // 27648
#define FL_SMEM (2 * FL_STG_SZ)   // 55296

__global__ __launch_bounds__(128, 3) void flash_bf()
{
    extern __shared__ char smc[];
    const unsigned smb = (unsigned)__cvta_generic_to_shared(smc);
    const int tid = threadIdx.x, wid = tid >> 5, lane = tid & 31;
    const int g = lane >> 2, t = lane & 3;
    const int quad = lane >> 3, lrow = lane & 7;
    const int it = (int)gridDim.x - 1 - (int)blockIdx.x;   // heavy tiles first
    const int i0 = it * 64;
    const int h = blockIdx.y, b = blockIdx.z;
    const float slope_l2 = exp2f(-0.5f * (float)(h + 1)) * 1.44269504f;
    const float sscale   = 0.125f * 1.44269504f;

    const unsigned lmoff = (unsigned)(((quad & 1) * 8 + lrow) * VRB + (quad >> 1) * 16);
    const unsigned vrow  = (unsigned)(lane & 15);
    const unsigned vc16  = (unsigned)(lane >> 4) * 16;

#define FL_LOAD_TILE(j0_, sbase_)                                              \
    {                                                                          \
        size_t kb_ = ((size_t)(b * Nq + (j0_)) * Hq + h) * DHq;                \
        _Pragma("unroll")                                                      \
        for (int itr_ = 0; itr_ < 4; itr_++) {                                 \
            int idx_ = itr_ * 128 + tid;                                       \
            int row_ = idx_ >> 3, ch_ = idx_ & 7;                              \
            size_t src_ = kb_ + (size_t)row_ * HDq + ch_ * 8;                  \
            unsigned so_ = (unsigned)(row_ * VRB + ch_ * 16);                  \
            CP_A16((sbase_) + 0 * FL_PL + so_, g_kb0 + src_);                  \
            CP_A16((sbase_) + 1 * FL_PL + so_, g_kb1 + src_);                  \
            CP_A16((sbase_) + 2 * FL_PL + so_, g_vh0 + src_);                  \
        }                                                                      \
    }

    // ---- prologue: stage Q[64][64] through stage-0 smem, extract fragments ----
    unsigned qf0[4][4], qf1[4][4];
    {
        size_t qb = ((size_t)(b * Nq + i0) * Hq + h) * DHq;
#pragma unroll
        for (int itr = 0; itr < 4; itr++) {
            int idx = itr * 128 + tid;
            int row = idx >> 3, ch = idx & 7;
            size_t src = qb + (size_t)row * HDq + ch * 8;
            CP_A16(smb + (unsigned)(row * VRB + ch * 16), g_qb0 + src);
            CP_A16(smb + (unsigned)FL_PL + (unsigned)(row * VRB + ch * 16), g_qb1 + src);
        }
        CP_COMMIT();
        CP_WAIT0();
        __syncthreads();
#pragma unroll
        for (int kt = 0; kt < 4; kt++) {
            unsigned qo = smb + (unsigned)(wid * 16) * VRB + lmoff + kt * 32;
            LDSM_X4(qf0[kt][0], qf0[kt][1], qf0[kt][2], qf0[kt][3], qo);
            LDSM_X4(qf1[kt][0], qf1[kt][1], qf1[kt][2], qf1[kt][3], qo + FL_PL);
        }
        __syncthreads();   // Q reads done before K/V pipeline reuses stage 0
    }

    float o[8][4] = {};
    float m0 = -1e30f, m1 = -1e30f, l0 = 0.f, l1 = 0.f;

    const int njt = it + 1;

    FL_LOAD_TILE(0, smb);
    CP_COMMIT();

    for (int jt = 0; jt < njt; jt++) {
        const int j0 = jt * 64;

        if (jt + 1 < njt) {
            FL_LOAD_TILE(j0 + 64, smb + (unsigned)(((jt + 1) & 1) * FL_STG_SZ));
            CP_COMMIT();
            CP_WAIT1();
        } else {
            CP_WAIT0();
        }
        __syncthreads();

        const unsigned kstg = smb + (unsigned)((jt & 1) * FL_STG_SZ);

        // ---- S = Q @ K^T (bf16x3) ----
        float s[8][4] = {};
#pragma unroll
        for (int kt = 0; kt < 4; kt++) {
            unsigned kb0[4][4], kb1[4][4];
#pragma unroll
            for (int grp = 0; grp < 4; grp++) {
                unsigned ko = kstg + (unsigned)(grp * 16) * VRB + lmoff + kt * 32;
                LDSM_X4(kb0[grp][0], kb0[grp][1], kb0[grp][2], kb0[grp][3], ko);
                LDSM_X4(kb1[grp][0], kb1[grp][1], kb1[grp][2], kb1[grp][3], ko + FL_PL);
            }
#pragma unroll
            for (int nt = 0; nt < 8; nt++)
                MMA_BF16(s[nt], qf0[kt], kb0[nt >> 1][nt & 1], kb0[nt >> 1][(nt & 1) + 2]);
#pragma unroll
            for (int nt = 0; nt < 8; nt++)
                MMA_BF16(s[nt], qf1[kt], kb0[nt >> 1][nt & 1], kb0[nt >> 1][(nt & 1) + 2]);
#pragma unroll
            for (int nt = 0; nt < 8; nt++)
                MMA_BF16(s[nt], qf0[kt], kb1[nt >> 1][nt & 1], kb1[nt >> 1][(nt & 1) + 2]);
        }

        // ---- scale + ALiBi(-slope*j only; row term cancels in softmax) ----
        float bj[16];
#pragma unroll
        for (int c8 = 0; c8 < 16; c8++)
            bj[c8] = -slope_l2 * (float)(j0 + (c8 >> 1) * 8 + 2 * t + (c8 & 1));
#pragma unroll
        for (int nt = 0; nt < 8; nt++)
#pragma unroll
            for (int e = 0; e < 4; e++)
                s[nt][e] = fmaf(s[nt][e], sscale, bj[nt * 2 + (e & 1)]);

        if (jt == njt - 1) {   // causal: only the diagonal tile masks
            const int ig0 = i0 + wid * 16 + g;
#pragma unroll
            for (int nt = 0; nt < 8; nt++)
#pragma unroll
                for (int e = 0; e < 4; e++) {
                    int jg = j0 + nt * 8 + 2 * t + (e & 1);
                    int ig = ig0 + ((e & 2) ? 8 : 0);
                    if (jg > ig) s[nt][e] = -1e30f;
                }
        }

        // ---- row stats ----
        float rmax0 = -1e30f, rmax1 = -1e30f;
#pragma unroll
        for (int nt = 0; nt < 8; nt++) {
            rmax0 = fmaxf(rmax0, fmaxf(s[nt][0], s[nt][1]));
            rmax1 = fmaxf(rmax1, fmaxf(s[nt][2], s[nt][3]));
        }
        rmax0 = fmaxf(rmax0, __shfl_xor_sync(0xffffffffu, rmax0, 1));
        rmax0 = fmaxf(rmax0, __shfl_xor_sync(0xffffffffu, rmax0, 2));
        rmax1 = fmaxf(rmax1, __shfl_xor_sync(0xffffffffu, rmax1, 1));
        rmax1 = fmaxf(rmax1, __shfl_xor_sync(0xffffffffu, rmax1, 2));
        float mn0 = fmaxf(m0, rmax0), mn1 = fmaxf(m1, rmax1);
        float f0 = ex2(m0 - mn0), f1 = ex2(m1 - mn1);
        m0 = mn0; m1 = mn1;

        float rs0 = 0.f, rs1 = 0.f;
#pragma unroll
        for (int nt = 0; nt < 8; nt++) {
            float p0_ = ex2(s[nt][0] - mn0), p1_ = ex2(s[nt][1] - mn0);
            float p2_ = ex2(s[nt][2] - mn1), p3_ = ex2(s[nt][3] - mn1);
            s[nt][0] = p0_; s[nt][1] = p1_; s[nt][2] = p2_; s[nt][3] = p3_;
            rs0 += p0_ + p1_; rs1 += p2_ + p3_;
        }
        rs0 += __shfl_xor_sync(0xffffffffu, rs0, 1);
        rs0 += __shfl_xor_sync(0xffffffffu, rs0, 2);
        rs1 += __shfl_xor_sync(0xffffffffu, rs1, 1);
        rs1 += __shfl_xor_sync(0xffffffffu, rs1, 2);
        l0 = l0 * f0 + rs0;
        l1 = l1 * f1 + rs1;
#pragma unroll
        for (int nt = 0; nt < 8; nt++) {
            o[nt][0] *= f0; o[nt][1] *= f0;
            o[nt][2] *= f1; o[nt][3] *= f1;
        }

        // ---- O += P @ V : P fp16 (in regs), V single fp16 plane, 1 pass ----
#pragma unroll
        for (int kt = 0; kt < 4; kt++) {
            unsigned p0[4];
            PK_HF2(p0[0], s[2 * kt][0],     s[2 * kt][1]);
            PK_HF2(p0[1], s[2 * kt][2],     s[2 * kt][3]);
            PK_HF2(p0[2], s[2 * kt + 1][0], s[2 * kt + 1][1]);
            PK_HF2(p0[3], s[2 * kt + 1][2], s[2 * kt + 1][3]);

            unsigned vb0[4][4];
#pragma unroll
            for (int dg = 0; dg < 4; dg++) {
                unsigned vo = kstg + 2 * FL_PL +
                              (unsigned)((kt * 16 + vrow) * VRB) + (unsigned)(dg * 32) + vc16;
                LDSM_T_X4(vb0[dg][0], vb0[dg][1], vb0[dg][2], vb0[dg][3], vo);
            }
#pragma unroll
            for (int nt = 0; nt < 8; nt++)
                MMA_F16(o[nt], p0, vb0[nt >> 1][(nt & 1) * 2], vb0[nt >> 1][(nt & 1) * 2 + 1]);
        }
        __syncthreads();   // all reads of stage (jt&1) done before it is refilled
    }

    // ---- normalize + write bf16 split planes ----
    float inv0 = 1.f / l0, inv1 = 1.f / l1;
    const int ig0 = i0 + wid * 16 + g;
#pragma unroll
    for (int nt = 0; nt < 8; nt++) {
        int d = nt * 8 + 2 * t;
        size_t idx0 = ((size_t)(b * Nq + ig0) * Hq + h) * DHq + d;
        size_t idx1 = idx0 + (size_t)8 * HDq;
        float v0 = o[nt][0] * inv0, v1 = o[nt][1] * inv0;
        float v2 = o[nt][2] * inv1, v3 = o[nt][3] * inv1;
        float h0 = bf_round(v0), h1 = bf_round(v1);
        float h2 = bf_round(v2), h3 = bf_round(v3);
        unsigned u;
        PK_BF2(u, h0, h1);           *(unsigned*)(g_ab0 + idx0) = u;
        PK_BF2(u, v0 - h0, v1 - h1); *(unsigned*)(g_ab1 + idx0) = u;
        PK_BF2(u, h2, h3);           *(unsigned*)(g_ab0 + idx1) = u;
        PK_BF2(u, v2 - h2, v3 - h3); *(unsigned*)(g_ab1 + idx1) = u;
    }
#undef FL_LOAD_TILE
}

// ---------------------------------------------------------------------------
extern "C" void kernel_launch(void* const* d_in, const int* in_sizes, int n_in,
                              void* d_out, int out_size)
{
    (void)in_sizes; (void)n_in; (void)out_size;
    const float* x  = (const float*)d_in[0];
    const float* Wq = (const float*)d_in[1];
    const float* Wk = (const float*)d_in[2];
    const float* Wv = (const float*)d_in[3];
    const float* Wo = (const float*)d_in[4];
    const float* bo = (const float*)d_in[5];
    float* out = (float*)d_out;

    cudaFuncSetAttribute(qkv_gemm_p, cudaFuncAttributeMaxDynamicSharedMemorySize, GEMMP_SMEM);
    cudaFuncSetAttribute(out_proj_p, cudaFuncAttributeMaxDynamicSharedMemorySize, GEMMP_SMEM);
    cudaFuncSetAttribute(flash_bf,   cudaFuncAttributeMaxDynamicSharedMemorySize, FL_SMEM);

    split_x_b<<<Mq * Dq / 4 / 256, 256>>>(x);
    split_wT_all<<<dim3(16, 16, 4), 256>>>(Wq, Wk, Wv, Wo);

    qkv_gemm_p<<<dim3(24, 32), 256, GEMMP_SMEM>>>();
    flash_bf<<<dim3(32, Hq, Bq), 128, FL_SMEM>>>();
    out_proj_p<<<dim3(8, 32), 256, GEMMP_SMEM>>>(bo, out);
}

// round 17
// speedup vs baseline: 1.4621x; 1.4621x over previous
#include <cuda_runtime.h>
#include <cuda_bf16.h>
#include <cuda_fp16.h>

#define Bq 2
#define Nq 2048
#define Hq 16
#define DHq 64
#define Dq 1024
#define HDq (Hq * DHq)   // 1024
#define Mq (Bq * Nq)     // 4096

#define PLX ((size_t)Mq * Dq)
#define PLW ((size_t)Dq * Dq)
#define PLA ((size_t)Mq * HDq)

// bf16 split planes
__device__ __nv_bfloat16 g_xb0[PLX], g_xb1[PLX];
__device__ __nv_bfloat16 g_wtb[8 * PLW];          // 4 weights x 2 planes, transposed [n][k]
__device__ __nv_bfloat16 g_qb0[PLA], g_qb1[PLA];
__device__ __nv_bfloat16 g_kb0[PLA], g_kb1[PLA];
__device__ __half        g_vh0[PLA], g_vh1[PLA];  // V planes in fp16 (for fp16 PV path)
__device__ __nv_bfloat16 g_ab0[PLA], g_ab1[PLA];

// ---------------------------------------------------------------------------
// helpers
// ---------------------------------------------------------------------------
__device__ __forceinline__ float bf_round(float x)
{
    return __bfloat162float(__float2bfloat16(x));
}

__device__ __forceinline__ float hf_round(float x)
{
    return __half2float(__float2half_rn(x));
}

__device__ __forceinline__ float ex2(float x)
{
    float r;
    asm("ex2.approx.f32 %0, %1;" : "=f"(r) : "f"(x));
    return r;
}

#define PK_BF2(d, a, b) \
    asm("cvt.rn.bf16x2.f32 %0, %1, %2;" : "=r"(d) : "f"(b), "f"(a))
#define PK_HF2(d, a, b) \
    asm("cvt.rn.f16x2.f32 %0, %1, %2;" : "=r"(d) : "f"(b), "f"(a))

#define MMA_BF16(d, a, b0_, b1_)                                              \
    asm volatile("mma.sync.aligned.m16n8k16.row.col.f32.bf16.bf16.f32 "       \
                 "{%0,%1,%2,%3}, {%4,%5,%6,%7}, {%8,%9}, {%0,%1,%2,%3};"      \
                 : "+f"(d[0]), "+f"(d[1]), "+f"(d[2]), "+f"(d[3])             \
                 : "r"(a[0]), "r"(a[1]), "r"(a[2]), "r"(a[3]),                \
                   "r"(b0_), "r"(b1_))

#define MMA_F16(d, a, b0_, b1_)                                               \
    asm volatile("mma.sync.aligned.m16n8k16.row.col.f32.f16.f16.f32 "         \
                 "{%0,%1,%2,%3}, {%4,%5,%6,%7}, {%8,%9}, {%0,%1,%2,%3};"      \
                 : "+f"(d[0]), "+f"(d[1]), "+f"(d[2]), "+f"(d[3])             \
                 : "r"(a[0]), "r"(a[1]), "r"(a[2]), "r"(a[3]),                \
                   "r"(b0_), "r"(b1_))

#define LDSM_X4(r0, r1, r2, r3, addr)                                         \
    asm volatile("ldmatrix.sync.aligned.m8n8.x4.shared.b16 {%0,%1,%2,%3}, [%4];" \
                 : "=r"(r0), "=r"(r1), "=r"(r2), "=r"(r3) : "r"(addr))

#define LDSM_T_X4(r0, r1, r2, r3, addr)                                       \
    asm volatile("ldmatrix.sync.aligned.m8n8.x4.trans.shared.b16 {%0,%1,%2,%3}, [%4];" \
                 : "=r"(r0), "=r"(r1), "=r"(r2), "=r"(r3) : "r"(addr))

#define CP_A16(dst, src) \
    asm volatile("cp.async.cg.shared.global [%0], [%1], 16;" :: "r"(dst), "l"(src))
#define CP_COMMIT() asm volatile("cp.async.commit_group;")
#define CP_WAIT0()  asm volatile("cp.async.wait_group 0;" ::: "memory")
#define CP_WAIT1()  asm volatile("cp.async.wait_group 1;" ::: "memory")

// ---------------------------------------------------------------------------
// split kernels
// ---------------------------------------------------------------------------
__global__ __launch_bounds__(256) void split_x_b(const float* __restrict__ in)
{
    size_t i = (size_t)blockIdx.x * 256 + threadIdx.x;   // over float4
    float4 v = ((const float4*)in)[i];
    float h0 = bf_round(v.x), h1 = bf_round(v.y), h2 = bf_round(v.z), h3 = bf_round(v.w);
    unsigned u;
    PK_BF2(u, h0, h1);                 *(unsigned*)(g_xb0 + i * 4)     = u;
    PK_BF2(u, h2, h3);                 *(unsigned*)(g_xb0 + i * 4 + 2) = u;
    PK_BF2(u, v.x - h0, v.y - h1);     *(unsigned*)(g_xb1 + i * 4)     = u;
    PK_BF2(u, v.z - h2, v.w - h3);     *(unsigned*)(g_xb1 + i * 4 + 2) = u;
}

// all 4 weights in one launch: transpose + split via smem tile
__global__ __launch_bounds__(256) void split_wT_all(const float* __restrict__ Wq,
                                                    const float* __restrict__ Wk,
                                                    const float* __restrict__ Wv,
                                                    const float* __restrict__ Wo)
{
    __shared__ float ts[64][68];
    const int w = blockIdx.z;
    const float* W = (w == 0) ? Wq : (w == 1) ? Wk : (w == 2) ? Wv : Wo;
    const int tid = threadIdx.x;
    const int n0 = blockIdx.x * 64, k0 = blockIdx.y * 64;

#pragma unroll
    for (int i = 0; i < 4; i++) {
        int idx = i * 256 + tid;
        int kr = idx >> 4, c4 = idx & 15;
        float4 v = *(const float4*)(W + (size_t)(k0 + kr) * Dq + n0 + c4 * 4);
        ts[c4 * 4 + 0][kr] = v.x;
        ts[c4 * 4 + 1][kr] = v.y;
        ts[c4 * 4 + 2][kr] = v.z;
        ts[c4 * 4 + 3][kr] = v.w;
    }
    __syncthreads();

    const int n = tid >> 2, kc = (tid & 3) * 16;
    unsigned u0[8], u1[8];
#pragma unroll
    for (int j = 0; j < 8; j++) {
        float v0 = ts[n][kc + 2 * j], v1 = ts[n][kc + 2 * j + 1];
        float h0 = bf_round(v0), h1 = bf_round(v1);
        PK_BF2(u0[j], h0, h1);
        PK_BF2(u1[j], v0 - h0, v1 - h1);
    }
    __nv_bfloat16* d0 = g_wtb + (size_t)(w * 2 + 0) * PLW + (size_t)(n0 + n) * Dq + k0 + kc;
    __nv_bfloat16* d1 = g_wtb + (size_t)(w * 2 + 1) * PLW + (size_t)(n0 + n) * Dq + k0 + kc;
    *(uint4*)(d0)     = make_uint4(u0[0], u0[1], u0[2], u0[3]);
    *(uint4*)(d0 + 8) = make_uint4(u0[4], u0[5], u0[6], u0[7]);
    *(uint4*)(d1)     = make_uint4(u1[0], u1[1], u1[2], u1[3]);
    *(uint4*)(d1 + 8) = make_uint4(u1[4], u1[5], u1[6], u1[7]);
}

// ---------------------------------------------------------------------------
// bf16x3 m16n8k16 GEMM, BK=32, 2-stage cp.async (R10, proven).
// Epilogues: bf16 planes (Cb0) / fp16 planes (Ch0) / fp32 + bias (Cf).
// ---------------------------------------------------------------------------
#define TPL 10240
#define STAGE_B 40960
#define GEMMP_SMEM (2 * STAGE_B)   // 81920

__device__ __forceinline__ void gemm_pipe_bf(const __nv_bfloat16* __restrict__ Ab0,
                                             const __nv_bfloat16* __restrict__ Ab1,
                                             const __nv_bfloat16* __restrict__ Wb0,
                                             const __nv_bfloat16* __restrict__ Wb1,
                                             __nv_bfloat16* __restrict__ Cb0,
                                             __nv_bfloat16* __restrict__ Cb1,
                                             __half* __restrict__ Ch0,
                                             __half* __restrict__ Ch1,
                                             float* __restrict__ Cf,
                                             const float* __restrict__ bias,
                                             int rowBlk, int colBlk)
{
    extern __shared__ float sm[];
    const unsigned smb = (unsigned)__cvta_generic_to_shared(sm);
    const int tid = threadIdx.x;
    const int wid = tid >> 5, lane = tid & 31;
    const int g = lane >> 2, t = lane & 3;
    const int wm = (wid & 3) * 32, wn = (wid >> 2) * 64;

    const size_t arow = (size_t)rowBlk * 128;
    const int ccol = colBlk * 128;

    const int quad = lane >> 3, lrow = lane & 7;
    const unsigned lmoff = (unsigned)(((quad & 1) * 8 + lrow) * 80 + (quad >> 1) * 16);

    float acc[2][8][4] = {};

#define PREFB(st, k0)                                                          \
    {                                                                          \
        unsigned base = smb + (st) * STAGE_B;                                  \
        _Pragma("unroll")                                                      \
        for (int i_ = 0; i_ < 2; i_++) {                                       \
            int idx = tid * 2 + i_;                                            \
            int r = idx >> 2, c4 = idx & 3;                                    \
            unsigned so = (unsigned)(r * 80 + c4 * 16);                        \
            CP_A16(base + 0 * TPL + so, Ab0 + (arow + r) * Dq + (k0) + c4 * 8);\
            CP_A16(base + 1 * TPL + so, Ab1 + (arow + r) * Dq + (k0) + c4 * 8);\
            CP_A16(base + 2 * TPL + so, Wb0 + (size_t)(ccol + r) * Dq + (k0) + c4 * 8); \
            CP_A16(base + 3 * TPL + so, Wb1 + (size_t)(ccol + r) * Dq + (k0) + c4 * 8); \
        }                                                                      \
    }

    PREFB(0, 0);
    CP_COMMIT();

    const int nch = Dq / 32;   // 32
    for (int chn = 0; chn < nch; chn++) {
        if (chn + 1 < nch) {
            PREFB((chn + 1) & 1, (chn + 1) * 32);
            CP_COMMIT();
            CP_WAIT1();
        } else {
            CP_WAIT0();
        }
        __syncthreads();

        const unsigned stg = smb + (chn & 1) * STAGE_B;

#pragma unroll
        for (int half = 0; half < 2; half++) {
            const unsigned co = (unsigned)(half * 32);
            unsigned af0[2][4], af1[2][4];
#pragma unroll
            for (int mt = 0; mt < 2; mt++) {
                unsigned ao = stg + (unsigned)((wm + mt * 16) * 80) + lmoff + co;
                LDSM_X4(af0[mt][0], af0[mt][1], af0[mt][2], af0[mt][3], ao);
                LDSM_X4(af1[mt][0], af1[mt][1], af1[mt][2], af1[mt][3], ao + TPL);
            }
            unsigned bf0[4][4], bf1[4][4];
#pragma unroll
            for (int np = 0; np < 4; np++) {
                unsigned wo = stg + 2 * TPL + (unsigned)((wn + np * 16) * 80) + lmoff + co;
                LDSM_X4(bf0[np][0], bf0[np][1], bf0[np][2], bf0[np][3], wo);
                LDSM_X4(bf1[np][0], bf1[np][1], bf1[np][2], bf1[np][3], wo + TPL);
            }
#pragma unroll
            for (int mt = 0; mt < 2; mt++)
#pragma unroll
                for (int nt = 0; nt < 8; nt++)
                    MMA_BF16(acc[mt][nt], af0[mt], bf0[nt >> 1][nt & 1], bf0[nt >> 1][(nt & 1) + 2]);
#pragma unroll
            for (int mt = 0; mt < 2; mt++)
#pragma unroll
                for (int nt = 0; nt < 8; nt++)
                    MMA_BF16(acc[mt][nt], af1[mt], bf0[nt >> 1][nt & 1], bf0[nt >> 1][(nt & 1) + 2]);
#pragma unroll
            for (int mt = 0; mt < 2; mt++)
#pragma unroll
                for (int nt = 0; nt < 8; nt++)
                    MMA_BF16(acc[mt][nt], af0[mt], bf1[nt >> 1][nt & 1], bf1[nt >> 1][(nt & 1) + 2]);
        }
        __syncthreads();
    }

#pragma unroll
    for (int mt = 0; mt < 2; mt++) {
        size_t r0 = arow + wm + mt * 16 + g;
#pragma unroll
        for (int nt = 0; nt < 8; nt++) {
            int c = ccol + wn + nt * 8 + 2 * t;
            float v0 = acc[mt][nt][0], v1 = acc[mt][nt][1];
            float v2 = acc[mt][nt][2], v3 = acc[mt][nt][3];
            if (Ch0) {
                float h0 = hf_round(v0), h1 = hf_round(v1);
                float h2 = hf_round(v2), h3 = hf_round(v3);
                unsigned u;
                PK_HF2(u, h0, h1);           *(unsigned*)(Ch0 + r0 * Dq + c) = u;
                PK_HF2(u, v0 - h0, v1 - h1); *(unsigned*)(Ch1 + r0 * Dq + c) = u;
                PK_HF2(u, h2, h3);           *(unsigned*)(Ch0 + (r0 + 8) * Dq + c) = u;
                PK_HF2(u, v2 - h2, v3 - h3); *(unsigned*)(Ch1 + (r0 + 8) * Dq + c) = u;
            } else if (Cb0) {
                float h0 = bf_round(v0), h1 = bf_round(v1);
                float h2 = bf_round(v2), h3 = bf_round(v3);
                unsigned u;
                PK_BF2(u, h0, h1);           *(unsigned*)(Cb0 + r0 * Dq + c) = u;
                PK_BF2(u, v0 - h0, v1 - h1); *(unsigned*)(Cb1 + r0 * Dq + c) = u;
                PK_BF2(u, h2, h3);           *(unsigned*)(Cb0 + (r0 + 8) * Dq + c) = u;
                PK_BF2(u, v2 - h2, v3 - h3); *(unsigned*)(Cb1 + (r0 + 8) * Dq + c) = u;
            } else {
                float b0 = bias[c], b1 = bias[c + 1];
                *(float2*)(Cf + r0 * Dq + c)       = make_float2(v0 + b0, v1 + b1);
                *(float2*)(Cf + (r0 + 8) * Dq + c) = make_float2(v2 + b0, v3 + b1);
            }
        }
    }
#undef PREFB
}

__global__ __launch_bounds__(256, 2) void qkv_gemm_p()
{
    int w = blockIdx.x >> 3, colBlk = blockIdx.x & 7;
    __nv_bfloat16* C0 = (w == 0) ? g_qb0 : (w == 1) ? g_kb0 : nullptr;
    __nv_bfloat16* C1 = (w == 0) ? g_qb1 : (w == 1) ? g_kb1 : nullptr;
    __half* H0 = (w == 2) ? g_vh0 : nullptr;
    __half* H1 = (w == 2) ? g_vh1 : nullptr;
    gemm_pipe_bf(g_xb0, g_xb1,
                 g_wtb + (size_t)(w * 2) * PLW, g_wtb + (size_t)(w * 2 + 1) * PLW,
                 C0, C1, H0, H1, nullptr, nullptr, blockIdx.y, colBlk);
}

__global__ __launch_bounds__(256, 2) void out_proj_p(const float* __restrict__ bo,
                                                     float* __restrict__ out)
{
    gemm_pipe_bf(g_ab0, g_ab1,
                 g_wtb + (size_t)6 * PLW, g_wtb + (size_t)7 * PLW,
                 nullptr, nullptr, nullptr, nullptr, out, bo, blockIdx.y, blockIdx.x);
}

// ---------------------------------------------------------------------------
// flash attention: S in bf16x3, P single fp16, V fp16 x2 (PV = 2 passes).
// BR=64 / 4 warps; Q frags persistent; 2-stage K/V ring; diag-only causal.
// ---------------------------------------------------------------------------
#define VRB 144
#define FL_PL 9216
#define FL_STG_SZ (4 * FL_PL) // 36864
#define FL_SMEM (2 * FL_STG_SZ)   // 73728

__global__ __launch_bounds__(128, 3) void flash_bf()
{
    extern __shared__ char smc[];
    const unsigned smb = (unsigned)__cvta_generic_to_shared(smc);
    const int tid = threadIdx.x, wid = tid >> 5, lane = tid & 31;
    const int g = lane >> 2, t = lane & 3;
    const int quad = lane >> 3, lrow = lane & 7;
    const int it = (int)gridDim.x - 1 - (int)blockIdx.x;   // heavy tiles first
    const int i0 = it * 64;
    const int h = blockIdx.y, b = blockIdx.z;
    const float slope_l2 = exp2f(-0.5f * (float)(h + 1)) * 1.44269504f;
    const float sscale   = 0.125f * 1.44269504f;

    const unsigned lmoff = (unsigned)(((quad & 1) * 8 + lrow) * VRB + (quad >> 1) * 16);
    const unsigned vrow  = (unsigned)(lane & 15);
    const unsigned vc16  = (unsigned)(lane >> 4) * 16;

#define FL_LOAD_TILE(j0_, sbase_)                                              \
    {                                                                          \
        size_t kb_ = ((size_t)(b * Nq + (j0_)) * Hq + h) * DHq;                \
        _Pragma("unroll")                                                      \
        for (int itr_ = 0; itr_ < 4; itr_++) {                                 \
            int idx_ = itr_ * 128 + tid;                                       \
            int row_ = idx_ >> 3, ch_ = idx_ & 7;                              \
            size_t src_ = kb_ + (size_t)row_ * HDq + ch_ * 8;                  \
            unsigned so_ = (unsigned)(row_ * VRB + ch_ * 16);                  \
            CP_A16((sbase_) + 0 * FL_PL + so_, g_kb0 + src_);                  \
            CP_A16((sbase_) + 1 * FL_PL + so_, g_kb1 + src_);                  \
            CP_A16((sbase_) + 2 * FL_PL + so_, g_vh0 + src_);                  \
            CP_A16((sbase_) + 3 * FL_PL + so_, g_vh1 + src_);                  \
        }                                                                      \
    }

    // ---- prologue: stage Q[64][64] through stage-0 smem, extract fragments ----
    unsigned qf0[4][4], qf1[4][4];
    {
        size_t qb = ((size_t)(b * Nq + i0) * Hq + h) * DHq;
#pragma unroll
        for (int itr = 0; itr < 4; itr++) {
            int idx = itr * 128 + tid;
            int row = idx >> 3, ch = idx & 7;
            size_t src = qb + (size_t)row * HDq + ch * 8;
            CP_A16(smb + (unsigned)(row * VRB + ch * 16), g_qb0 + src);
            CP_A16(smb + (unsigned)FL_PL + (unsigned)(row * VRB + ch * 16), g_qb1 + src);
        }
        CP_COMMIT();
        CP_WAIT0();
        __syncthreads();
#pragma unroll
        for (int kt = 0; kt < 4; kt++) {
            unsigned qo = smb + (unsigned)(wid * 16) * VRB + lmoff + kt * 32;
            LDSM_X4(qf0[kt][0], qf0[kt][1], qf0[kt][2], qf0[kt][3], qo);
            LDSM_X4(qf1[kt][0], qf1[kt][1], qf1[kt][2], qf1[kt][3], qo + FL_PL);
        }
        __syncthreads();   // Q reads done before K/V pipeline reuses stage 0
    }

    float o[8][4] = {};
    float m0 = -1e30f, m1 = -1e30f, l0 = 0.f, l1 = 0.f;

    const int njt = it + 1;

    FL_LOAD_TILE(0, smb);
    CP_COMMIT();

    for (int jt = 0; jt < njt; jt++) {
        const int j0 = jt * 64;

        if (jt + 1 < njt) {
            FL_LOAD_TILE(j0 + 64, smb + (unsigned)(((jt + 1) & 1) * FL_STG_SZ));
            CP_COMMIT();
            CP_WAIT1();
        } else {
            CP_WAIT0();
        }
        __syncthreads();

        const unsigned kstg = smb + (unsigned)((jt & 1) * FL_STG_SZ);

        // ---- S = Q @ K^T (bf16x3) ----
        float s[8][4] = {};
#pragma unroll
        for (int kt = 0; kt < 4; kt++) {
            unsigned kb0[4][4], kb1[4][4];
#pragma unroll
            for (int grp = 0; grp < 4; grp++) {
                unsigned ko = kstg + (unsigned)(grp * 16) * VRB + lmoff + kt * 32;
                LDSM_X4(kb0[grp][0], kb0[grp][1], kb0[grp][2], kb0[grp][3], ko);
                LDSM_X4(kb1[grp][0], kb1[grp][1], kb1[grp][2], kb1[grp][3], ko + FL_PL);
            }
#pragma unroll
            for (int nt = 0; nt < 8; nt++)
                MMA_BF16(s[nt], qf0[kt], kb0[nt >> 1][nt & 1], kb0[nt >> 1][(nt & 1) + 2]);
#pragma unroll
            for (int nt = 0; nt < 8; nt++)
                MMA_BF16(s[nt], qf1[kt], kb0[nt >> 1][nt & 1], kb0[nt >> 1][(nt & 1) + 2]);
#pragma unroll
            for (int nt = 0; nt < 8; nt++)
                MMA_BF16(s[nt], qf0[kt], kb1[nt >> 1][nt & 1], kb1[nt >> 1][(nt & 1) + 2]);
        }

        // ---- scale + ALiBi(-slope*j only; row term cancels in softmax) ----
        float bj[16];
#pragma unroll
        for (int c8 = 0; c8 < 16; c8++)
            bj[c8] = -slope_l2 * (float)(j0 + (c8 >> 1) * 8 + 2 * t + (c8 & 1));
#pragma unroll
        for (int nt = 0; nt < 8; nt++)
#pragma unroll
            for (int e = 0; e < 4; e++)
                s[nt][e] = fmaf(s[nt][e], sscale, bj[nt * 2 + (e & 1)]);

        if (jt == njt - 1) {   // causal: only the diagonal tile masks
            const int ig0 = i0 + wid * 16 + g;
#pragma unroll
            for (int nt = 0; nt < 8; nt++)
#pragma unroll
                for (int e = 0; e < 4; e++) {
                    int jg = j0 + nt * 8 + 2 * t + (e & 1);
                    int ig = ig0 + ((e & 2) ? 8 : 0);
                    if (jg > ig) s[nt][e] = -1e30f;
                }
        }

        // ---- row stats ----
        float rmax0 = -1e30f, rmax1 = -1e30f;
#pragma unroll
        for (int nt = 0; nt < 8; nt++) {
            rmax0 = fmaxf(rmax0, fmaxf(s[nt][0], s[nt][1]));
            rmax1 = fmaxf(rmax1, fmaxf(s[nt][2], s[nt][3]));
        }
        rmax0 = fmaxf(rmax0, __shfl_xor_sync(0xffffffffu, rmax0, 1));
        rmax0 = fmaxf(rmax0, __shfl_xor_sync(0xffffffffu, rmax0, 2));
        rmax1 = fmaxf(rmax1, __shfl_xor_sync(0xffffffffu, rmax1, 1));
        rmax1 = fmaxf(rmax1, __shfl_xor_sync(0xffffffffu, rmax1, 2));
        float mn0 = fmaxf(m0, rmax0), mn1 = fmaxf(m1, rmax1);
        float f0 = ex2(m0 - mn0), f1 = ex2(m1 - mn1);
        m0 = mn0; m1 = mn1;

        float rs0 = 0.f, rs1 = 0.f;
#pragma unroll
        for (int nt = 0; nt < 8; nt++) {
            float p0_ = ex2(s[nt][0] - mn0), p1_ = ex2(s[nt][1] - mn0);
            float p2_ = ex2(s[nt][2] - mn1), p3_ = ex2(s[nt][3] - mn1);
            s[nt][0] = p0_; s[nt][1] = p1_; s[nt][2] = p2_; s[nt][3] = p3_;
            rs0 += p0_ + p1_; rs1 += p2_ + p3_;
        }
        rs0 += __shfl_xor_sync(0xffffffffu, rs0, 1);
        rs0 += __shfl_xor_sync(0xffffffffu, rs0, 2);
        rs1 += __shfl_xor_sync(0xffffffffu, rs1, 1);
        rs1 += __shfl_xor_sync(0xffffffffu, rs1, 2);
        l0 = l0 * f0 + rs0;
        l1 = l1 * f1 + rs1;
#pragma unroll
        for (int nt = 0; nt < 8; nt++) {
            o[nt][0] *= f0; o[nt][1] *= f0;
            o[nt][2] *= f1; o[nt][3] *= f1;
        }

        // ---- O += P @ V : P single fp16 (in regs), V fp16 x2 planes ----
#pragma unroll
        for (int kt = 0; kt < 4; kt++) {
            unsigned p0[4];
            PK_HF2(p0[0], s[2 * kt][0],     s[2 * kt][1]);
            PK_HF2(p0[1], s[2 * kt][2],     s[2 * kt][3]);
            PK_HF2(p0[2], s[2 * kt + 1][0], s[2 * kt + 1][1]);
            PK_HF2(p0[3], s[2 * kt + 1][2], s[2 * kt + 1][3]);

            unsigned vb0[4][4], vb1[4][4];
#pragma unroll
            for (int dg = 0; dg < 4; dg++) {
                unsigned vo = kstg + 2 * FL_PL +
                              (unsigned)((kt * 16 + vrow) * VRB) + (unsigned)(dg * 32) + vc16;
                LDSM_T_X4(vb0[dg][0], vb0[dg][1], vb0[dg][2], vb0[dg][3], vo);
                LDSM_T_X4(vb1[dg][0], vb1[dg][1], vb1[dg][2], vb1[dg][3], vo + FL_PL);
            }
#pragma unroll
            for (int nt = 0; nt < 8; nt++)
                MMA_F16(o[nt], p0, vb0[nt >> 1][(nt & 1) * 2], vb0[nt >> 1][(nt & 1) * 2 + 1]);
#pragma unroll
            for (int nt = 0; nt < 8; nt++)
                MMA_F16(o[nt], p0, vb1[nt >> 1][(nt & 1) * 2], vb1[nt >> 1][(nt & 1) * 2 + 1]);
        }
        __syncthreads();   // all reads of stage (jt&1) done before it is refilled
    }

    // ---- normalize + write bf16 split planes ----
    float inv0 = 1.f / l0, inv1 = 1.f / l1;
    const int ig0 = i0 + wid * 16 + g;
#pragma unroll
    for (int nt = 0; nt < 8; nt++) {
        int d = nt * 8 + 2 * t;
        size_t idx0 = ((size_t)(b * Nq + ig0) * Hq + h) * DHq + d;
        size_t idx1 = idx0 + (size_t)8 * HDq;
        float v0 = o[nt][0] * inv0, v1 = o[nt][1] * inv0;
        float v2 = o[nt][2] * inv1, v3 = o[nt][3] * inv1;
        float h0 = bf_round(v0), h1 = bf_round(v1);
        float h2 = bf_round(v2), h3 = bf_round(v3);
        unsigned u;
        PK_BF2(u, h0, h1);           *(unsigned*)(g_ab0 + idx0) = u;
        PK_BF2(u, v0 - h0, v1 - h1); *(unsigned*)(g_ab1 + idx0) = u;
        PK_BF2(u, h2, h3);           *(unsigned*)(g_ab0 + idx1) = u;
        PK_BF2(u, v2 - h2, v3 - h3); *(unsigned*)(g_ab1 + idx1) = u;
    }
#undef FL_LOAD_TILE
}

// ---------------------------------------------------------------------------
extern "C" void kernel_launch(void* const* d_in, const int* in_sizes, int n_in,
                              void* d_out, int out_size)
{
    (void)in_sizes; (void)n_in; (void)out_size;
    const float* x  = (const float*)d_in[0];
    const float* Wq = (const float*)d_in[1];
    const float* Wk = (const float*)d_in[2];
    const float* Wv = (const float*)d_in[3];
    const float* Wo = (const float*)d_in[4];
    const float* bo = (const float*)d_in[5];
    float* out = (float*)d_out;

    cudaFuncSetAttribute(qkv_gemm_p, cudaFuncAttributeMaxDynamicSharedMemorySize, GEMMP_SMEM);
    cudaFuncSetAttribute(out_proj_p, cudaFuncAttributeMaxDynamicSharedMemorySize, GEMMP_SMEM);
    cudaFuncSetAttribute(flash_bf,   cudaFuncAttributeMaxDynamicSharedMemorySize, FL_SMEM);

    split_x_b<<<Mq * Dq / 4 / 256, 256>>>(x);
    split_wT_all<<<dim3(16, 16, 4), 256>>>(Wq, Wk, Wv, Wo);

    qkv_gemm_p<<<dim3(24, 32), 256, GEMMP_SMEM>>>();
    flash_bf<<<dim3(32, Hq, Bq), 128, FL_SMEM>>>();
    out_proj_p<<<dim3(8, 32), 256, GEMMP_SMEM>>>(bo, out);
}